// round 12
// baseline (speedup 1.0000x reference)
#include <cuda_runtime.h>
#include <cuda_bf16.h>
#include <math.h>
#include <stdint.h>

#define T_TOK 2048
#define D_HID 1024
#define FF    512
#define NE    16
#define TOPK  4
#define CL    3
#define EPS   1e-5f
#define TK    (T_TOK*TOPK)

// ---------------- fp32 scratch ------------------------------------------------
__device__ float g_h1  [T_TOK*D_HID];
__device__ float g_res1[T_TOK*D_HID];
__device__ float g_bcx [T_TOK*3*D_HID];
__device__ float g_y   [T_TOK*D_HID];
__device__ float g_h2  [T_TOK*D_HID];
__device__ float g_ye  [TK*D_HID];
__device__ int   g_topi[TK];
__device__ float g_topw[TK];
__device__ int   g_counts[NE];
__device__ int   g_offsets[NE];
__device__ int   g_fill[NE];
__device__ int   g_rowtok[TK];
__device__ int   g_slot[TK];

// ---------------- bf16 hi/lo activation scratch --------------------------------
__device__ __nv_bfloat16 g_h1h [T_TOK*D_HID],  g_h1l [T_TOK*D_HID];
__device__ __nv_bfloat16 g_yph [T_TOK*D_HID],  g_ypl [T_TOK*D_HID];
__device__ __nv_bfloat16 g_h2h [T_TOK*D_HID],  g_h2l [T_TOK*D_HID];
__device__ __nv_bfloat16 g_acth[TK*FF],        g_actl[TK*FF];

// ---------------- PTX helpers --------------------------------------------------
__device__ __forceinline__ uint32_t smem_u32(const void* p) {
    uint32_t a;
    asm("{ .reg .u64 t; cvta.to.shared.u64 t, %1; cvt.u32.u64 %0, t; }" : "=r"(a) : "l"(p));
    return a;
}
#define CPASYNC(dst, src, sz) \
    asm volatile("cp.async.cg.shared.global [%0], [%1], 16, %2;" :: "r"(dst), "l"(src), "r"(sz))
#define CPCOMMIT() asm volatile("cp.async.commit_group;" ::: "memory")
#define CPWAIT0()  asm volatile("cp.async.wait_group 0;" ::: "memory")
#define LDSM4(r0,r1,r2,r3,addr) \
    asm volatile("ldmatrix.sync.aligned.m8n8.x4.shared.b16 {%0,%1,%2,%3}, [%4];" \
        : "=r"(r0),"=r"(r1),"=r"(r2),"=r"(r3) : "r"(addr))
#define MMA16816(d,a,b0,b1) \
    asm volatile("mma.sync.aligned.m16n8k16.row.col.f32.bf16.bf16.f32 " \
        "{%0,%1,%2,%3}, {%4,%5,%6,%7}, {%8,%9}, {%0,%1,%2,%3};" \
        : "+f"((d)[0]),"+f"((d)[1]),"+f"((d)[2]),"+f"((d)[3]) \
        : "r"((a)[0]),"r"((a)[1]),"r"((a)[2]),"r"((a)[3]), "r"(b0),"r"(b1))
#define LDS128F(v, addr) \
    asm volatile("ld.shared.v4.f32 {%0,%1,%2,%3}, [%4];" \
        : "=f"((v).x),"=f"((v).y),"=f"((v).z),"=f"((v).w) : "r"(addr))
#define STS128U(addr, a0,a1,a2,a3) \
    asm volatile("st.shared.v4.b32 [%0], {%1,%2,%3,%4};" \
        :: "r"(addr), "r"(a0),"r"(a1),"r"(a2),"r"(a3) : "memory")

// ---------------- fused add + rmsnorm (+ bf16 hi/lo emit) ----------------------
__global__ void norm_kernel(const float* __restrict__ x, const float* __restrict__ rin,
                            const float* __restrict__ w, float* __restrict__ hout,
                            float* __restrict__ rout,
                            __nv_bfloat16* __restrict__ hhi, __nv_bfloat16* __restrict__ hlo) {
    int t = blockIdx.x;
    int base = threadIdx.x * 4;
    size_t off = (size_t)t * D_HID + base;
    float4 xv = *(const float4*)(x + off);
    float4 rv = *(const float4*)(rin + off);
    float4 s;
    s.x = xv.x + rv.x; s.y = xv.y + rv.y; s.z = xv.z + rv.z; s.w = xv.w + rv.w;
    *(float4*)(rout + off) = s;
    float ss = s.x*s.x + s.y*s.y + s.z*s.z + s.w*s.w;
    #pragma unroll
    for (int o = 16; o > 0; o >>= 1) ss += __shfl_down_sync(0xffffffffu, ss, o);
    __shared__ float sm[8];
    __shared__ float s_inv;
    if ((threadIdx.x & 31) == 0) sm[threadIdx.x >> 5] = ss;
    __syncthreads();
    if (threadIdx.x == 0) {
        float tot = 0.f;
        #pragma unroll
        for (int i = 0; i < 8; i++) tot += sm[i];
        s_inv = rsqrtf(tot / (float)D_HID + EPS);
    }
    __syncthreads();
    float inv = s_inv;
    float4 wv = *(const float4*)(w + base);
    float o[4];
    o[0] = s.x*inv*wv.x; o[1] = s.y*inv*wv.y; o[2] = s.z*inv*wv.z; o[3] = s.w*inv*wv.w;
    *(float4*)(hout + off) = *(float4*)o;
    __nv_bfloat16 h[4], l[4];
    #pragma unroll
    for (int i = 0; i < 4; i++) {
        h[i] = __float2bfloat16(o[i]);
        l[i] = __float2bfloat16(o[i] - __bfloat162float(h[i]));
    }
    *(uint2*)(hhi + off) = *(uint2*)h;
    *(uint2*)(hlo + off) = *(uint2*)l;
}

// ---------------- split-bf16 mma.sync GEMM (512 thr / 16 warps) ---------------
// 128x128x32 tile; warp grid 4x4, warp tile 32x32.
// A: pre-split hi/lo bf16. B: fp32 -> hi/lo bf16 in-kernel.
// 3-term: Ahi*Bhi + Ahi*Blo + Alo*Bhi, fp32 accum.
// MODE 0 plain; MODE 1 MoE gemm1 + fused SiLU epilogue; MODE 2 MoE gemm2.
#define AHI_OFF 0u
#define ALO_OFF 8192u
#define BHI_OFF 16384u
#define BLO_OFF 24576u
#define BF32_OFF 32768u
#define STG 49152u

template<int MODE>
__global__ __launch_bounds__(512, 1)
void mma_gemm(const __nv_bfloat16* __restrict__ Ahi, const __nv_bfloat16* __restrict__ Alo,
              const float* __restrict__ Bf32, float* __restrict__ Cout, int N, int K) {
    extern __shared__ char smb[];
    int tid = threadIdx.x, lane = tid & 31, wid = tid >> 5;

    int cnt = T_TOK, ebase = 0;
    const float* bbase = Bf32;
    if (MODE > 0) {
        int e = blockIdx.z;
        cnt = g_counts[e]; ebase = g_offsets[e];
        bbase = Bf32 + (size_t)e * (size_t)N * K;
    }
    int m0 = blockIdx.y * 128;
    if (m0 >= cnt) return;
    int n0 = blockIdx.x * 128;

    uint32_t sb = smem_u32(smb);

    // ---- load mapping: row = tid>>2, q = tid&3 (16B bf16 chunk / 32B fp32) ----
    int lrow = tid >> 2;
    int q = tid & 3;
    const __nv_bfloat16 *ahp, *alp;
    uint32_t asz = 16;
    if (MODE == 0) {
        int r = m0 + lrow;
        ahp = Ahi + (size_t)r * K; alp = Alo + (size_t)r * K;
    } else if (MODE == 1) {
        int r = m0 + lrow; bool v = (r < cnt);
        int tok = v ? g_rowtok[ebase + r] : 0;
        asz = v ? 16u : 0u;
        ahp = Ahi + (size_t)tok * K; alp = Alo + (size_t)tok * K;
    } else {
        int r = m0 + lrow; bool v = (r < cnt);
        asz = v ? 16u : 0u;
        int rr = ebase + (v ? r : 0);
        ahp = Ahi + (size_t)rr * K; alp = Alo + (size_t)rr * K;
    }
    int wrow;
    if (MODE == 1) {
        int bx = blockIdx.x;   // grid.x = FF/64; 64 gate rows + 64 up rows
        wrow = (lrow < 64) ? (bx * 64 + lrow) : (FF + bx * 64 + (lrow - 64));
    } else {
        wrow = n0 + lrow;
    }
    const float* bfp = bbase + (size_t)wrow * K;

    uint32_t swr = (uint32_t)((lrow >> 1) & 3);
    uint32_t dA = (uint32_t)lrow * 64u + (((uint32_t)q ^ swr) << 4);
    uint32_t bq0 = (uint32_t)lrow * 128u + ((uint32_t)((q*2)   ^ (lrow & 7)) << 4);
    uint32_t bq1 = (uint32_t)lrow * 128u + ((uint32_t)((q*2+1) ^ (lrow & 7)) << 4);

    // ---- ldmatrix address offsets (4x4 warp grid, 32x32 warp tile) ----
    int wm0 = (wid & 3) * 32, wn0 = (wid >> 2) * 32;
    uint32_t a_off[2][2], b_off[2][2];
    #pragma unroll
    for (int mi = 0; mi < 2; mi++)
        #pragma unroll
        for (int ks = 0; ks < 2; ks++) {
            int r = wm0 + mi * 16 + (lane & 15);
            uint32_t kc = (uint32_t)(ks * 2 + (lane >> 4));
            a_off[mi][ks] = (uint32_t)r * 64u + ((kc ^ ((uint32_t)(r >> 1) & 3u)) << 4);
        }
    #pragma unroll
    for (int pr = 0; pr < 2; pr++)
        #pragma unroll
        for (int ks = 0; ks < 2; ks++) {
            int r = wn0 + pr * 16 + (lane & 7) + ((lane >> 4) ? 8 : 0);
            uint32_t kc = (uint32_t)(ks * 2 + ((lane >> 3) & 1));
            b_off[pr][ks] = (uint32_t)r * 64u + ((kc ^ ((uint32_t)(r >> 1) & 3u)) << 4);
        }

    float acc[2][4][4];
    #pragma unroll
    for (int mi = 0; mi < 2; mi++)
        #pragma unroll
        for (int nt = 0; nt < 4; nt++)
            #pragma unroll
            for (int p = 0; p < 4; p++) acc[mi][nt][p] = 0.f;

    int nch = K / 32;
    // prologue
    {
        uint32_t bb = sb;
        CPASYNC(bb + AHI_OFF + dA, (const char*)ahp + q * 16, asz);
        CPASYNC(bb + ALO_OFF + dA, (const char*)alp + q * 16, asz);
        const char* bs = (const char*)bfp + q * 32;
        CPASYNC(bb + BF32_OFF + bq0, bs,      16u);
        CPASYNC(bb + BF32_OFF + bq1, bs + 16, 16u);
        CPCOMMIT();
    }

    for (int ch = 0; ch < nch; ch++) {
        CPWAIT0();
        __syncthreads();
        uint32_t stb = sb + (uint32_t)(ch & 1) * STG;
        if (ch + 1 < nch) {
            uint32_t bb = sb + (uint32_t)((ch + 1) & 1) * STG;
            int aoff = (ch + 1) * 64 + q * 16;
            CPASYNC(bb + AHI_OFF + dA, (const char*)ahp + aoff, asz);
            CPASYNC(bb + ALO_OFF + dA, (const char*)alp + aoff, asz);
            const char* bs = (const char*)bfp + (ch + 1) * 128 + q * 32;
            CPASYNC(bb + BF32_OFF + bq0, bs,      16u);
            CPASYNC(bb + BF32_OFF + bq1, bs + 16, 16u);
            CPCOMMIT();
        }
        // convert B fp32 -> hi/lo bf16 (8 floats/thread)
        {
            float4 v0, v1;
            LDS128F(v0, stb + BF32_OFF + bq0);
            LDS128F(v1, stb + BF32_OFF + bq1);
            float f[8] = {v0.x, v0.y, v0.z, v0.w, v1.x, v1.y, v1.z, v1.w};
            uint32_t hi[4], lo[4];
            #pragma unroll
            for (int i = 0; i < 4; i++) {
                __nv_bfloat162 hp = __floats2bfloat162_rn(f[2*i], f[2*i+1]);
                uint32_t hb = *(uint32_t*)&hp;
                hi[i] = hb;
                float r0 = f[2*i]   - __uint_as_float(hb << 16);
                float r1 = f[2*i+1] - __uint_as_float(hb & 0xFFFF0000u);
                __nv_bfloat162 lp = __floats2bfloat162_rn(r0, r1);
                lo[i] = *(uint32_t*)&lp;
            }
            STS128U(stb + BHI_OFF + dA, hi[0], hi[1], hi[2], hi[3]);
            STS128U(stb + BLO_OFF + dA, lo[0], lo[1], lo[2], lo[3]);
        }
        __syncthreads();
        // ---- mma over stage s ----
        #pragma unroll
        for (int ks = 0; ks < 2; ks++) {
            uint32_t ah[2][4], al[2][4];
            #pragma unroll
            for (int mi = 0; mi < 2; mi++) {
                LDSM4(ah[mi][0], ah[mi][1], ah[mi][2], ah[mi][3], stb + AHI_OFF + a_off[mi][ks]);
                LDSM4(al[mi][0], al[mi][1], al[mi][2], al[mi][3], stb + ALO_OFF + a_off[mi][ks]);
            }
            #pragma unroll
            for (int pr = 0; pr < 2; pr++) {
                uint32_t bh0, bh1, bh2, bh3, bl0, bl1, bl2, bl3;
                LDSM4(bh0, bh1, bh2, bh3, stb + BHI_OFF + b_off[pr][ks]);
                LDSM4(bl0, bl1, bl2, bl3, stb + BLO_OFF + b_off[pr][ks]);
                #pragma unroll
                for (int mi = 0; mi < 2; mi++) {
                    MMA16816(acc[mi][pr*2],   ah[mi], bh0, bh1);
                    MMA16816(acc[mi][pr*2],   ah[mi], bl0, bl1);
                    MMA16816(acc[mi][pr*2],   al[mi], bh0, bh1);
                    MMA16816(acc[mi][pr*2+1], ah[mi], bh2, bh3);
                    MMA16816(acc[mi][pr*2+1], ah[mi], bl2, bl3);
                    MMA16816(acc[mi][pr*2+1], al[mi], bh2, bh3);
                }
            }
        }
    }

    int grp = lane >> 2, tig = lane & 3;
    if (MODE == 1) {
        // ---- fused SiLU epilogue via padded smem exchange ----
        __syncthreads();
        float* sp = (float*)smb;               // 128 x 132 fp32 = 67584 B
        #pragma unroll
        for (int mi = 0; mi < 2; mi++) {
            int r0i = wm0 + mi * 16 + grp;
            #pragma unroll
            for (int nt = 0; nt < 4; nt++) {
                int col = wn0 + nt * 8 + tig * 2;
                sp[r0i * 132 + col]         = acc[mi][nt][0];
                sp[r0i * 132 + col + 1]     = acc[mi][nt][1];
                sp[(r0i+8) * 132 + col]     = acc[mi][nt][2];
                sp[(r0i+8) * 132 + col + 1] = acc[mi][nt][3];
            }
        }
        __syncthreads();
        int bx = blockIdx.x;
        for (int i = tid; i < 128 * 64; i += 512) {
            int r = i >> 6, c = i & 63;
            if (m0 + r < cnt) {
                float gv = sp[r * 132 + c];
                float uv = sp[r * 132 + 64 + c];
                float v = (gv / (1.f + expf(-gv))) * uv;
                __nv_bfloat16 h = __float2bfloat16(v);
                __nv_bfloat16 l = __float2bfloat16(v - __bfloat162float(h));
                size_t orow = (size_t)(ebase + m0 + r) * FF + bx * 64 + c;
                g_acth[orow] = h;
                g_actl[orow] = l;
            }
        }
    } else {
        #pragma unroll
        for (int mi = 0; mi < 2; mi++) {
            int rl0 = wm0 + mi * 16 + grp;
            #pragma unroll
            for (int nt = 0; nt < 4; nt++) {
                int col = n0 + wn0 + nt * 8 + tig * 2;
                int r0i = m0 + rl0, r1i = r0i + 8;
                bool v0 = (MODE == 0) || (r0i < cnt);
                bool v1 = (MODE == 0) || (r1i < cnt);
                size_t g0 = (size_t)((MODE == 0) ? r0i : ebase + r0i) * N + col;
                size_t g1 = (size_t)((MODE == 0) ? r1i : ebase + r1i) * N + col;
                if (v0) { float2 p = make_float2(acc[mi][nt][0], acc[mi][nt][1]); *(float2*)(Cout + g0) = p; }
                if (v1) { float2 p = make_float2(acc[mi][nt][2], acc[mi][nt][3]); *(float2*)(Cout + g1) = p; }
            }
        }
    }
}

// ---------------- short conv + C-gate -> ypre hi/lo ---------------------------
__global__ void conv_kernel(const float* __restrict__ convw) {
    int i = blockIdx.x * blockDim.x + threadIdx.x;
    if (i >= T_TOK * D_HID) return;
    int t = i / D_HID, d = i % D_HID;
    float w0 = convw[d*CL + 0], w1 = convw[d*CL + 1], w2 = convw[d*CL + 2];
    const float* bc = g_bcx;
    size_t r0 = (size_t)t * 3 * D_HID;
    float acc = w2 * bc[r0 + d] * bc[r0 + 2*D_HID + d];
    if (t >= 1) { size_t r1 = r0 - 3*D_HID; acc += w1 * bc[r1 + d] * bc[r1 + 2*D_HID + d]; }
    if (t >= 2) { size_t r2 = r0 - 6*D_HID; acc += w0 * bc[r2 + d] * bc[r2 + 2*D_HID + d]; }
    float v = bc[r0 + D_HID + d] * acc;
    __nv_bfloat16 h = __float2bfloat16(v);
    g_yph[i] = h;
    g_ypl[i] = __float2bfloat16(v - __bfloat162float(h));
}

// ---------------- gating ------------------------------------------------------
__global__ void zero_counts_kernel() {
    if (threadIdx.x < NE) g_counts[threadIdx.x] = 0;
}

__global__ void gate_kernel(const float* __restrict__ h2, const float* __restrict__ gw,
                            const float* __restrict__ gb) {
    int t = blockIdx.x;
    int warp = threadIdx.x >> 5, lane = threadIdx.x & 31;
    const float* hr = h2 + (size_t)t * D_HID;
    const float* wr = gw + (size_t)warp * D_HID;
    float p = 0.f;
    for (int k = lane; k < D_HID; k += 32) p += hr[k] * wr[k];
    #pragma unroll
    for (int o = 16; o > 0; o >>= 1) p += __shfl_down_sync(0xffffffffu, p, o);
    __shared__ float s_logit[NE];
    if (lane == 0) s_logit[warp] = p;
    __syncthreads();
    if (threadIdx.x == 0) {
        float sc[NE], ch[NE];
        bool used[NE];
        #pragma unroll
        for (int e = 0; e < NE; e++) {
            float s = 1.f / (1.f + expf(-s_logit[e]));
            sc[e] = s; ch[e] = s + gb[e]; used[e] = false;
        }
        int idx[TOPK]; float wsum = 0.f;
        #pragma unroll
        for (int k = 0; k < TOPK; k++) {
            float best = -1e30f; int bi = 0;
            #pragma unroll
            for (int e = 0; e < NE; e++)
                if (!used[e] && ch[e] > best) { best = ch[e]; bi = e; }
            used[bi] = true; idx[k] = bi; wsum += sc[bi];
        }
        float inv = 1.f / (wsum + 1e-20f);
        #pragma unroll
        for (int k = 0; k < TOPK; k++) {
            g_topi[t*TOPK + k] = idx[k];
            g_topw[t*TOPK + k] = sc[idx[k]] * inv;
            atomicAdd(&g_counts[idx[k]], 1);
        }
    }
}

__global__ void scan_kernel() {
    if (threadIdx.x == 0) {
        int acc = 0;
        for (int e = 0; e < NE; e++) { g_offsets[e] = acc; acc += g_counts[e]; }
    }
    if (threadIdx.x < NE) g_fill[threadIdx.x] = 0;
}

__global__ void fill_kernel() {
    int i = blockIdx.x * blockDim.x + threadIdx.x;
    if (i >= TK) return;
    int e = g_topi[i];
    int pos = g_offsets[e] + atomicAdd(&g_fill[e], 1);
    g_rowtok[pos] = i / TOPK;
    g_slot[i] = pos;
}

// ---------------- combine ------------------------------------------------------
__global__ void combine_kernel(float* __restrict__ out) {
    int i = blockIdx.x * blockDim.x + threadIdx.x;
    if (i >= T_TOK * D_HID) return;
    int t = i / D_HID, d = i % D_HID;
    float s = 0.f;
    #pragma unroll
    for (int k = 0; k < TOPK; k++)
        s += g_topw[t*TOPK + k] * g_ye[(size_t)g_slot[t*TOPK + k] * D_HID + d];
    out[i] = s;   // SCALE = 1.0
}

// ---------------- launch -------------------------------------------------------
#define GEMM_SMEM (2*49152)

template<typename T> static T* sym(const void* s) {
    void* p = nullptr;
    cudaGetSymbolAddress(&p, s);
    return (T*)p;
}

extern "C" void kernel_launch(void* const* d_in, const int* in_sizes, int n_in,
                              void* d_out, int out_size) {
    const float* hs    = (const float*)d_in[0];
    const float* res   = (const float*)d_in[1];
    const float* opw   = (const float*)d_in[2];
    const float* ffnw  = (const float*)d_in[3];
    const float* inw   = (const float*)d_in[4];
    const float* convw = (const float*)d_in[5];
    const float* outw  = (const float*)d_in[6];
    const float* gw    = (const float*)d_in[7];
    const float* gb    = (const float*)d_in[8];
    const float* w1    = (const float*)d_in[9];
    const float* w2    = (const float*)d_in[10];
    float* out = (float*)d_out;
    float* res_out = out + (size_t)T_TOK * D_HID;

    float* p_h1   = sym<float>(&g_h1);
    float* p_res1 = sym<float>(&g_res1);
    float* p_bcx  = sym<float>(&g_bcx);
    float* p_y    = sym<float>(&g_y);
    float* p_h2   = sym<float>(&g_h2);
    float* p_ye   = sym<float>(&g_ye);
    __nv_bfloat16* p_h1h  = sym<__nv_bfloat16>(&g_h1h);
    __nv_bfloat16* p_h1l  = sym<__nv_bfloat16>(&g_h1l);
    __nv_bfloat16* p_yph  = sym<__nv_bfloat16>(&g_yph);
    __nv_bfloat16* p_ypl  = sym<__nv_bfloat16>(&g_ypl);
    __nv_bfloat16* p_h2h  = sym<__nv_bfloat16>(&g_h2h);
    __nv_bfloat16* p_h2l  = sym<__nv_bfloat16>(&g_h2l);
    __nv_bfloat16* p_acth = sym<__nv_bfloat16>(&g_acth);
    __nv_bfloat16* p_actl = sym<__nv_bfloat16>(&g_actl);

    cudaFuncSetAttribute(mma_gemm<0>, cudaFuncAttributeMaxDynamicSharedMemorySize, GEMM_SMEM);
    cudaFuncSetAttribute(mma_gemm<1>, cudaFuncAttributeMaxDynamicSharedMemorySize, GEMM_SMEM);
    cudaFuncSetAttribute(mma_gemm<2>, cudaFuncAttributeMaxDynamicSharedMemorySize, GEMM_SMEM);

    // 1) h1 = rmsnorm(hs + res); res1 = hs + res
    norm_kernel<<<T_TOK, 256>>>(hs, res, opw, p_h1, p_res1, p_h1h, p_h1l);

    // 2) bcx = h1 @ in_proj^T
    mma_gemm<0><<<dim3(3*D_HID/128, T_TOK/128, 1), 512, GEMM_SMEM>>>(
        p_h1h, p_h1l, inw, p_bcx, 3*D_HID, D_HID);

    // 3) short conv + C gate -> ypre hi/lo
    conv_kernel<<<(T_TOK*D_HID + 255)/256, 256>>>(convw);

    // 4) y = ypre @ out_proj^T
    mma_gemm<0><<<dim3(D_HID/128, T_TOK/128, 1), 512, GEMM_SMEM>>>(
        p_yph, p_ypl, outw, p_y, D_HID, D_HID);

    // 5) h2 = rmsnorm(y + res1); residual out
    norm_kernel<<<T_TOK, 256>>>(p_y, p_res1, ffnw, p_h2, res_out, p_h2h, p_h2l);

    // 6-9) gating + bucketing
    zero_counts_kernel<<<1, 32>>>();
    gate_kernel<<<T_TOK, NE*32>>>(p_h2, gw, gb);
    scan_kernel<<<1, 32>>>();
    fill_kernel<<<(TK + 255)/256, 256>>>();

    // 10) gemm1 + fused SiLU -> act hi/lo
    mma_gemm<1><<<dim3(FF/64, T_TOK/128, NE), 512, GEMM_SMEM>>>(
        p_h2h, p_h2l, w1, (float*)0, 2*FF, D_HID);

    // 11) ye = act @ w2[e]^T; combine
    mma_gemm<2><<<dim3(D_HID/128, T_TOK/128, NE), 512, GEMM_SMEM>>>(
        p_acth, p_actl, w2, p_ye, D_HID, FF);
    combine_kernel<<<(T_TOK*D_HID + 255)/256, 256>>>(out);
}

// round 14
// speedup vs baseline: 1.0973x; 1.0973x over previous
#include <cuda_runtime.h>
#include <cuda_bf16.h>
#include <math.h>
#include <stdint.h>

#define T_TOK 2048
#define D_HID 1024
#define FF    512
#define NE    16
#define TOPK  4
#define CL    3
#define EPS   1e-5f
#define TK    (T_TOK*TOPK)

// ---------------- fp32 scratch ------------------------------------------------
__device__ float g_h1  [T_TOK*D_HID];
__device__ float g_res1[T_TOK*D_HID];
__device__ float g_bcx [T_TOK*3*D_HID];
__device__ float g_y   [T_TOK*D_HID];
__device__ float g_h2  [T_TOK*D_HID];
__device__ float g_ye  [TK*D_HID];
__device__ int   g_topi[TK];
__device__ float g_topw[TK];
__device__ int   g_counts[NE];
__device__ int   g_offsets[NE];
__device__ int   g_fill[NE];
__device__ int   g_rowtok[TK];
__device__ int   g_slot[TK];

// ---------------- bf16 hi/lo activation scratch --------------------------------
__device__ __nv_bfloat16 g_h1h [T_TOK*D_HID],  g_h1l [T_TOK*D_HID];
__device__ __nv_bfloat16 g_yph [T_TOK*D_HID],  g_ypl [T_TOK*D_HID];
__device__ __nv_bfloat16 g_h2h [T_TOK*D_HID],  g_h2l [T_TOK*D_HID];
__device__ __nv_bfloat16 g_acth[TK*FF],        g_actl[TK*FF];

// ---------------- PTX helpers --------------------------------------------------
__device__ __forceinline__ uint32_t smem_u32(const void* p) {
    uint32_t a;
    asm("{ .reg .u64 t; cvta.to.shared.u64 t, %1; cvt.u32.u64 %0, t; }" : "=r"(a) : "l"(p));
    return a;
}
#define CPASYNC(dst, src, sz) \
    asm volatile("cp.async.cg.shared.global [%0], [%1], 16, %2;" :: "r"(dst), "l"(src), "r"(sz))
#define CPCOMMIT() asm volatile("cp.async.commit_group;" ::: "memory")
#define CPWAIT0()  asm volatile("cp.async.wait_group 0;" ::: "memory")
#define LDSM4(r0,r1,r2,r3,addr) \
    asm volatile("ldmatrix.sync.aligned.m8n8.x4.shared.b16 {%0,%1,%2,%3}, [%4];" \
        : "=r"(r0),"=r"(r1),"=r"(r2),"=r"(r3) : "r"(addr))
#define MMA16816(d,a,b0,b1) \
    asm volatile("mma.sync.aligned.m16n8k16.row.col.f32.bf16.bf16.f32 " \
        "{%0,%1,%2,%3}, {%4,%5,%6,%7}, {%8,%9}, {%0,%1,%2,%3};" \
        : "+f"((d)[0]),"+f"((d)[1]),"+f"((d)[2]),"+f"((d)[3]) \
        : "r"((a)[0]),"r"((a)[1]),"r"((a)[2]),"r"((a)[3]), "r"(b0),"r"(b1))
#define LDS128F(v, addr) \
    asm volatile("ld.shared.v4.f32 {%0,%1,%2,%3}, [%4];" \
        : "=f"((v).x),"=f"((v).y),"=f"((v).z),"=f"((v).w) : "r"(addr))
#define STS128U(addr, a0,a1,a2,a3) \
    asm volatile("st.shared.v4.b32 [%0], {%1,%2,%3,%4};" \
        :: "r"(addr), "r"(a0),"r"(a1),"r"(a2),"r"(a3) : "memory")

// ---------------- fused add + rmsnorm (+ bf16 hi/lo emit) ----------------------
__global__ void norm_kernel(const float* __restrict__ x, const float* __restrict__ rin,
                            const float* __restrict__ w, float* __restrict__ hout,
                            float* __restrict__ rout,
                            __nv_bfloat16* __restrict__ hhi, __nv_bfloat16* __restrict__ hlo) {
    int t = blockIdx.x;
    int base = threadIdx.x * 4;
    size_t off = (size_t)t * D_HID + base;
    float4 xv = *(const float4*)(x + off);
    float4 rv = *(const float4*)(rin + off);
    float4 s;
    s.x = xv.x + rv.x; s.y = xv.y + rv.y; s.z = xv.z + rv.z; s.w = xv.w + rv.w;
    *(float4*)(rout + off) = s;
    float ss = s.x*s.x + s.y*s.y + s.z*s.z + s.w*s.w;
    #pragma unroll
    for (int o = 16; o > 0; o >>= 1) ss += __shfl_down_sync(0xffffffffu, ss, o);
    __shared__ float sm[8];
    __shared__ float s_inv;
    if ((threadIdx.x & 31) == 0) sm[threadIdx.x >> 5] = ss;
    __syncthreads();
    if (threadIdx.x == 0) {
        float tot = 0.f;
        #pragma unroll
        for (int i = 0; i < 8; i++) tot += sm[i];
        s_inv = rsqrtf(tot / (float)D_HID + EPS);
    }
    __syncthreads();
    float inv = s_inv;
    float4 wv = *(const float4*)(w + base);
    float o[4];
    o[0] = s.x*inv*wv.x; o[1] = s.y*inv*wv.y; o[2] = s.z*inv*wv.z; o[3] = s.w*inv*wv.w;
    *(float4*)(hout + off) = *(float4*)o;
    __nv_bfloat16 h[4], l[4];
    #pragma unroll
    for (int i = 0; i < 4; i++) {
        h[i] = __float2bfloat16(o[i]);
        l[i] = __float2bfloat16(o[i] - __bfloat162float(h[i]));
    }
    *(uint2*)(hhi + off) = *(uint2*)h;
    *(uint2*)(hlo + off) = *(uint2*)l;
}

// ---------------- split-bf16 mma.sync GEMM (512 thr / 16 warps) ---------------
// 128x128x32 tile; warp grid 4x4, warp tile 32x32. ONE barrier per chunk:
//   wait(own cp groups) -> convert(own B data) -> sync -> issue next loads -> mma
// Safe because each thread converts exactly the bytes it cp.async'd, and the
// post-barrier cp.async issue cannot race pre-barrier ldsm reads.
// 3-term: Ahi*Bhi + Ahi*Blo + Alo*Bhi, fp32 accum.
// MODE 0 plain; MODE 1 MoE gemm1 + fused SiLU epilogue; MODE 2 MoE gemm2.
#define AHI_OFF 0u
#define ALO_OFF 8192u
#define BHI_OFF 16384u
#define BLO_OFF 24576u
#define BF32_OFF 32768u
#define STG 49152u

template<int MODE>
__global__ __launch_bounds__(512, 1)
void mma_gemm(const __nv_bfloat16* __restrict__ Ahi, const __nv_bfloat16* __restrict__ Alo,
              const float* __restrict__ Bf32, float* __restrict__ Cout, int N, int K) {
    extern __shared__ char smb[];
    int tid = threadIdx.x, lane = tid & 31, wid = tid >> 5;

    int cnt = T_TOK, ebase = 0;
    const float* bbase = Bf32;
    if (MODE > 0) {
        int e = blockIdx.z;
        cnt = g_counts[e]; ebase = g_offsets[e];
        bbase = Bf32 + (size_t)e * (size_t)N * K;
    }
    int m0 = blockIdx.y * 128;
    if (m0 >= cnt) return;
    int n0 = blockIdx.x * 128;

    uint32_t sb = smem_u32(smb);

    // ---- load mapping: row = tid>>2, q = tid&3 ----
    int lrow = tid >> 2;
    int q = tid & 3;
    const __nv_bfloat16 *ahp, *alp;
    uint32_t asz = 16;
    if (MODE == 0) {
        int r = m0 + lrow;
        ahp = Ahi + (size_t)r * K; alp = Alo + (size_t)r * K;
    } else if (MODE == 1) {
        int r = m0 + lrow; bool v = (r < cnt);
        int tok = v ? g_rowtok[ebase + r] : 0;
        asz = v ? 16u : 0u;
        ahp = Ahi + (size_t)tok * K; alp = Alo + (size_t)tok * K;
    } else {
        int r = m0 + lrow; bool v = (r < cnt);
        asz = v ? 16u : 0u;
        int rr = ebase + (v ? r : 0);
        ahp = Ahi + (size_t)rr * K; alp = Alo + (size_t)rr * K;
    }
    int wrow;
    if (MODE == 1) {
        int bx = blockIdx.x;   // grid.x = FF/64; 64 gate rows + 64 up rows
        wrow = (lrow < 64) ? (bx * 64 + lrow) : (FF + bx * 64 + (lrow - 64));
    } else {
        wrow = n0 + lrow;
    }
    const float* bfp = bbase + (size_t)wrow * K;

    uint32_t swr = (uint32_t)((lrow >> 1) & 3);
    uint32_t dA = (uint32_t)lrow * 64u + (((uint32_t)q ^ swr) << 4);
    uint32_t bq0 = (uint32_t)lrow * 128u + ((uint32_t)((q*2)   ^ (lrow & 7)) << 4);
    uint32_t bq1 = (uint32_t)lrow * 128u + ((uint32_t)((q*2+1) ^ (lrow & 7)) << 4);

    // ---- ldmatrix address offsets ----
    int wm0 = (wid & 3) * 32, wn0 = (wid >> 2) * 32;
    uint32_t a_off[2][2], b_off[2][2];
    #pragma unroll
    for (int mi = 0; mi < 2; mi++)
        #pragma unroll
        for (int ks = 0; ks < 2; ks++) {
            int r = wm0 + mi * 16 + (lane & 15);
            uint32_t kc = (uint32_t)(ks * 2 + (lane >> 4));
            a_off[mi][ks] = (uint32_t)r * 64u + ((kc ^ ((uint32_t)(r >> 1) & 3u)) << 4);
        }
    #pragma unroll
    for (int pr = 0; pr < 2; pr++)
        #pragma unroll
        for (int ks = 0; ks < 2; ks++) {
            int r = wn0 + pr * 16 + (lane & 7) + ((lane >> 4) ? 8 : 0);
            uint32_t kc = (uint32_t)(ks * 2 + ((lane >> 3) & 1));
            b_off[pr][ks] = (uint32_t)r * 64u + ((kc ^ ((uint32_t)(r >> 1) & 3u)) << 4);
        }

    float acc[2][4][4];
    #pragma unroll
    for (int mi = 0; mi < 2; mi++)
        #pragma unroll
        for (int nt = 0; nt < 4; nt++)
            #pragma unroll
            for (int p = 0; p < 4; p++) acc[mi][nt][p] = 0.f;

    int nch = K / 32;
    // prologue: issue loads for chunk 0
    {
        uint32_t bb = sb;
        CPASYNC(bb + AHI_OFF + dA, (const char*)ahp + q * 16, asz);
        CPASYNC(bb + ALO_OFF + dA, (const char*)alp + q * 16, asz);
        const char* bs = (const char*)bfp + q * 32;
        CPASYNC(bb + BF32_OFF + bq0, bs,      16u);
        CPASYNC(bb + BF32_OFF + bq1, bs + 16, 16u);
        CPCOMMIT();
    }

    for (int ch = 0; ch < nch; ch++) {
        uint32_t stb = sb + (uint32_t)(ch & 1) * STG;
        CPWAIT0();                           // own groups done (stage ch landed for me)
        // convert OWN B fp32 -> hi/lo bf16 (no barrier needed before this)
        {
            float4 v0, v1;
            LDS128F(v0, stb + BF32_OFF + bq0);
            LDS128F(v1, stb + BF32_OFF + bq1);
            float f[8] = {v0.x, v0.y, v0.z, v0.w, v1.x, v1.y, v1.z, v1.w};
            uint32_t hi[4], lo[4];
            #pragma unroll
            for (int i = 0; i < 4; i++) {
                __nv_bfloat162 hp = __floats2bfloat162_rn(f[2*i], f[2*i+1]);
                uint32_t hb = *(uint32_t*)&hp;
                hi[i] = hb;
                float r0 = f[2*i]   - __uint_as_float(hb << 16);
                float r1 = f[2*i+1] - __uint_as_float(hb & 0xFFFF0000u);
                __nv_bfloat162 lp = __floats2bfloat162_rn(r0, r1);
                lo[i] = *(uint32_t*)&lp;
            }
            STS128U(stb + BHI_OFF + dA, hi[0], hi[1], hi[2], hi[3]);
            STS128U(stb + BLO_OFF + dA, lo[0], lo[1], lo[2], lo[3]);
        }
        __syncthreads();                     // the ONE barrier: converts visible, A landed
        // issue next chunk's loads (post-barrier: cannot race prior ldsm reads)
        if (ch + 1 < nch) {
            uint32_t bb = sb + (uint32_t)((ch + 1) & 1) * STG;
            int aoff = (ch + 1) * 64 + q * 16;
            CPASYNC(bb + AHI_OFF + dA, (const char*)ahp + aoff, asz);
            CPASYNC(bb + ALO_OFF + dA, (const char*)alp + aoff, asz);
            const char* bs = (const char*)bfp + (ch + 1) * 128 + q * 32;
            CPASYNC(bb + BF32_OFF + bq0, bs,      16u);
            CPASYNC(bb + BF32_OFF + bq1, bs + 16, 16u);
            CPCOMMIT();
        }
        // ---- mma over stage ch (warps skew here; tensor stays fed) ----
        #pragma unroll
        for (int ks = 0; ks < 2; ks++) {
            uint32_t ah[2][4], al[2][4];
            #pragma unroll
            for (int mi = 0; mi < 2; mi++) {
                LDSM4(ah[mi][0], ah[mi][1], ah[mi][2], ah[mi][3], stb + AHI_OFF + a_off[mi][ks]);
                LDSM4(al[mi][0], al[mi][1], al[mi][2], al[mi][3], stb + ALO_OFF + a_off[mi][ks]);
            }
            #pragma unroll
            for (int pr = 0; pr < 2; pr++) {
                uint32_t bh0, bh1, bh2, bh3, bl0, bl1, bl2, bl3;
                LDSM4(bh0, bh1, bh2, bh3, stb + BHI_OFF + b_off[pr][ks]);
                LDSM4(bl0, bl1, bl2, bl3, stb + BLO_OFF + b_off[pr][ks]);
                #pragma unroll
                for (int mi = 0; mi < 2; mi++) {
                    MMA16816(acc[mi][pr*2],   ah[mi], bh0, bh1);
                    MMA16816(acc[mi][pr*2],   ah[mi], bl0, bl1);
                    MMA16816(acc[mi][pr*2],   al[mi], bh0, bh1);
                    MMA16816(acc[mi][pr*2+1], ah[mi], bh2, bh3);
                    MMA16816(acc[mi][pr*2+1], ah[mi], bl2, bl3);
                    MMA16816(acc[mi][pr*2+1], al[mi], bh2, bh3);
                }
            }
        }
    }

    int grp = lane >> 2, tig = lane & 3;
    if (MODE == 1) {
        // ---- fused SiLU epilogue via padded smem exchange ----
        __syncthreads();
        float* sp = (float*)smb;               // 128 x 132 fp32 = 67584 B
        #pragma unroll
        for (int mi = 0; mi < 2; mi++) {
            int r0i = wm0 + mi * 16 + grp;
            #pragma unroll
            for (int nt = 0; nt < 4; nt++) {
                int col = wn0 + nt * 8 + tig * 2;
                sp[r0i * 132 + col]         = acc[mi][nt][0];
                sp[r0i * 132 + col + 1]     = acc[mi][nt][1];
                sp[(r0i+8) * 132 + col]     = acc[mi][nt][2];
                sp[(r0i+8) * 132 + col + 1] = acc[mi][nt][3];
            }
        }
        __syncthreads();
        int bx = blockIdx.x;
        for (int i = tid; i < 128 * 64; i += 512) {
            int r = i >> 6, c = i & 63;
            if (m0 + r < cnt) {
                float gv = sp[r * 132 + c];
                float uv = sp[r * 132 + 64 + c];
                float v = (gv / (1.f + expf(-gv))) * uv;
                __nv_bfloat16 h = __float2bfloat16(v);
                __nv_bfloat16 l = __float2bfloat16(v - __bfloat162float(h));
                size_t orow = (size_t)(ebase + m0 + r) * FF + bx * 64 + c;
                g_acth[orow] = h;
                g_actl[orow] = l;
            }
        }
    } else {
        #pragma unroll
        for (int mi = 0; mi < 2; mi++) {
            int rl0 = wm0 + mi * 16 + grp;
            #pragma unroll
            for (int nt = 0; nt < 4; nt++) {
                int col = n0 + wn0 + nt * 8 + tig * 2;
                int r0i = m0 + rl0, r1i = r0i + 8;
                bool v0 = (MODE == 0) || (r0i < cnt);
                bool v1 = (MODE == 0) || (r1i < cnt);
                size_t g0 = (size_t)((MODE == 0) ? r0i : ebase + r0i) * N + col;
                size_t g1 = (size_t)((MODE == 0) ? r1i : ebase + r1i) * N + col;
                if (v0) { float2 p = make_float2(acc[mi][nt][0], acc[mi][nt][1]); *(float2*)(Cout + g0) = p; }
                if (v1) { float2 p = make_float2(acc[mi][nt][2], acc[mi][nt][3]); *(float2*)(Cout + g1) = p; }
            }
        }
    }
}

// ---------------- short conv + C-gate -> ypre hi/lo ---------------------------
__global__ void conv_kernel(const float* __restrict__ convw) {
    int i = blockIdx.x * blockDim.x + threadIdx.x;
    if (i >= T_TOK * D_HID) return;
    int t = i / D_HID, d = i % D_HID;
    float w0 = convw[d*CL + 0], w1 = convw[d*CL + 1], w2 = convw[d*CL + 2];
    const float* bc = g_bcx;
    size_t r0 = (size_t)t * 3 * D_HID;
    float acc = w2 * bc[r0 + d] * bc[r0 + 2*D_HID + d];
    if (t >= 1) { size_t r1 = r0 - 3*D_HID; acc += w1 * bc[r1 + d] * bc[r1 + 2*D_HID + d]; }
    if (t >= 2) { size_t r2 = r0 - 6*D_HID; acc += w0 * bc[r2 + d] * bc[r2 + 2*D_HID + d]; }
    float v = bc[r0 + D_HID + d] * acc;
    __nv_bfloat16 h = __float2bfloat16(v);
    g_yph[i] = h;
    g_ypl[i] = __float2bfloat16(v - __bfloat162float(h));
}

// ---------------- gating ------------------------------------------------------
__global__ void zero_counts_kernel() {
    if (threadIdx.x < NE) g_counts[threadIdx.x] = 0;
}

__global__ void gate_kernel(const float* __restrict__ h2, const float* __restrict__ gw,
                            const float* __restrict__ gb) {
    int t = blockIdx.x;
    int warp = threadIdx.x >> 5, lane = threadIdx.x & 31;
    const float* hr = h2 + (size_t)t * D_HID;
    const float* wr = gw + (size_t)warp * D_HID;
    float p = 0.f;
    for (int k = lane; k < D_HID; k += 32) p += hr[k] * wr[k];
    #pragma unroll
    for (int o = 16; o > 0; o >>= 1) p += __shfl_down_sync(0xffffffffu, p, o);
    __shared__ float s_logit[NE];
    if (lane == 0) s_logit[warp] = p;
    __syncthreads();
    if (threadIdx.x == 0) {
        float sc[NE], ch[NE];
        bool used[NE];
        #pragma unroll
        for (int e = 0; e < NE; e++) {
            float s = 1.f / (1.f + expf(-s_logit[e]));
            sc[e] = s; ch[e] = s + gb[e]; used[e] = false;
        }
        int idx[TOPK]; float wsum = 0.f;
        #pragma unroll
        for (int k = 0; k < TOPK; k++) {
            float best = -1e30f; int bi = 0;
            #pragma unroll
            for (int e = 0; e < NE; e++)
                if (!used[e] && ch[e] > best) { best = ch[e]; bi = e; }
            used[bi] = true; idx[k] = bi; wsum += sc[bi];
        }
        float inv = 1.f / (wsum + 1e-20f);
        #pragma unroll
        for (int k = 0; k < TOPK; k++) {
            g_topi[t*TOPK + k] = idx[k];
            g_topw[t*TOPK + k] = sc[idx[k]] * inv;
            atomicAdd(&g_counts[idx[k]], 1);
        }
    }
}

__global__ void scan_kernel() {
    if (threadIdx.x == 0) {
        int acc = 0;
        for (int e = 0; e < NE; e++) { g_offsets[e] = acc; acc += g_counts[e]; }
    }
    if (threadIdx.x < NE) g_fill[threadIdx.x] = 0;
}

__global__ void fill_kernel() {
    int i = blockIdx.x * blockDim.x + threadIdx.x;
    if (i >= TK) return;
    int e = g_topi[i];
    int pos = g_offsets[e] + atomicAdd(&g_fill[e], 1);
    g_rowtok[pos] = i / TOPK;
    g_slot[i] = pos;
}

// ---------------- combine ------------------------------------------------------
__global__ void combine_kernel(float* __restrict__ out) {
    int i = blockIdx.x * blockDim.x + threadIdx.x;
    if (i >= T_TOK * D_HID) return;
    int t = i / D_HID, d = i % D_HID;
    float s = 0.f;
    #pragma unroll
    for (int k = 0; k < TOPK; k++)
        s += g_topw[t*TOPK + k] * g_ye[(size_t)g_slot[t*TOPK + k] * D_HID + d];
    out[i] = s;   // SCALE = 1.0
}

// ---------------- launch -------------------------------------------------------
#define GEMM_SMEM (2*49152)

template<typename T> static T* sym(const void* s) {
    void* p = nullptr;
    cudaGetSymbolAddress(&p, s);
    return (T*)p;
}

extern "C" void kernel_launch(void* const* d_in, const int* in_sizes, int n_in,
                              void* d_out, int out_size) {
    const float* hs    = (const float*)d_in[0];
    const float* res   = (const float*)d_in[1];
    const float* opw   = (const float*)d_in[2];
    const float* ffnw  = (const float*)d_in[3];
    const float* inw   = (const float*)d_in[4];
    const float* convw = (const float*)d_in[5];
    const float* outw  = (const float*)d_in[6];
    const float* gw    = (const float*)d_in[7];
    const float* gb    = (const float*)d_in[8];
    const float* w1    = (const float*)d_in[9];
    const float* w2    = (const float*)d_in[10];
    float* out = (float*)d_out;
    float* res_out = out + (size_t)T_TOK * D_HID;

    float* p_h1   = sym<float>(&g_h1);
    float* p_res1 = sym<float>(&g_res1);
    float* p_bcx  = sym<float>(&g_bcx);
    float* p_y    = sym<float>(&g_y);
    float* p_h2   = sym<float>(&g_h2);
    float* p_ye   = sym<float>(&g_ye);
    __nv_bfloat16* p_h1h  = sym<__nv_bfloat16>(&g_h1h);
    __nv_bfloat16* p_h1l  = sym<__nv_bfloat16>(&g_h1l);
    __nv_bfloat16* p_yph  = sym<__nv_bfloat16>(&g_yph);
    __nv_bfloat16* p_ypl  = sym<__nv_bfloat16>(&g_ypl);
    __nv_bfloat16* p_h2h  = sym<__nv_bfloat16>(&g_h2h);
    __nv_bfloat16* p_h2l  = sym<__nv_bfloat16>(&g_h2l);
    __nv_bfloat16* p_acth = sym<__nv_bfloat16>(&g_acth);
    __nv_bfloat16* p_actl = sym<__nv_bfloat16>(&g_actl);

    cudaFuncSetAttribute(mma_gemm<0>, cudaFuncAttributeMaxDynamicSharedMemorySize, GEMM_SMEM);
    cudaFuncSetAttribute(mma_gemm<1>, cudaFuncAttributeMaxDynamicSharedMemorySize, GEMM_SMEM);
    cudaFuncSetAttribute(mma_gemm<2>, cudaFuncAttributeMaxDynamicSharedMemorySize, GEMM_SMEM);

    // 1) h1 = rmsnorm(hs + res); res1 = hs + res
    norm_kernel<<<T_TOK, 256>>>(hs, res, opw, p_h1, p_res1, p_h1h, p_h1l);

    // 2) bcx = h1 @ in_proj^T
    mma_gemm<0><<<dim3(3*D_HID/128, T_TOK/128, 1), 512, GEMM_SMEM>>>(
        p_h1h, p_h1l, inw, p_bcx, 3*D_HID, D_HID);

    // 3) short conv + C gate -> ypre hi/lo
    conv_kernel<<<(T_TOK*D_HID + 255)/256, 256>>>(convw);

    // 4) y = ypre @ out_proj^T
    mma_gemm<0><<<dim3(D_HID/128, T_TOK/128, 1), 512, GEMM_SMEM>>>(
        p_yph, p_ypl, outw, p_y, D_HID, D_HID);

    // 5) h2 = rmsnorm(y + res1); residual out
    norm_kernel<<<T_TOK, 256>>>(p_y, p_res1, ffnw, p_h2, res_out, p_h2h, p_h2l);

    // 6-9) gating + bucketing
    zero_counts_kernel<<<1, 32>>>();
    gate_kernel<<<T_TOK, NE*32>>>(p_h2, gw, gb);
    scan_kernel<<<1, 32>>>();
    fill_kernel<<<(TK + 255)/256, 256>>>();

    // 10) gemm1 + fused SiLU -> act hi/lo
    mma_gemm<1><<<dim3(FF/64, T_TOK/128, NE), 512, GEMM_SMEM>>>(
        p_h2h, p_h2l, w1, (float*)0, 2*FF, D_HID);

    // 11) ye = act @ w2[e]^T; combine
    mma_gemm<2><<<dim3(D_HID/128, T_TOK/128, NE), 512, GEMM_SMEM>>>(
        p_acth, p_actl, w2, p_ye, D_HID, FF);
    combine_kernel<<<(T_TOK*D_HID + 255)/256, 256>>>(out);
}